// round 2
// baseline (speedup 1.0000x reference)
#include <cuda_runtime.h>

// StateQueue: pure data-movement. Shapes fixed by the problem.
#define Bv   16
#define Nv   900
#define Dv   256
#define QMv  4
#define QPv  4
#define NPv  6
#define Tv   4
#define TM1v 3

// Region sizes (float elements)
#define S0 (Bv*QMv*Nv*Dv)   /* mq  3,686,400 */
#define S1 (Bv*QPv*NPv*Dv)  /* pq     98,304 */
#define S2 (Bv*QPv*Dv)      /* eq     16,384 */
#define S3 (Bv*QMv)         /* per        64 */
#define S4 (Bv*TM1v*Nv)     /* mm     43,200 */
#define S5 (Bv*TM1v*Nv*Dv)  /* me 11,059,200 */
#define S6 (Bv*TM1v)        /* pm         48 */
#define S7 (Bv*TM1v*Dv)     /* pe     12,288 */

#define R1 (S0)
#define R2 (R1+S1)
#define R3 (R2+S2)
#define R4 (R3+S3)
#define R5 (R4+S4)
#define R6 (R5+S5)
#define R7 (R6+S6)
#define TOTAL (R7+S7)
#define TOTAL4 (TOTAL/4)

__global__ void state_queue_kernel(
    const float* __restrict__ motion_query,      // (B,N,D)
    const float* __restrict__ plan_query,        // (B,NP,D)
    const float* __restrict__ ego_status,        // (B,D)
    const float* __restrict__ motion_queue,      // (B,QM,N,D)
    const float* __restrict__ plan_queue,        // (B,QP,NP,D)
    const float* __restrict__ ego_status_queue,  // (B,QP,D)
    const int*   __restrict__ period,            // (B,QM)
    const int*   __restrict__ mask,              // (B,) bool->int32
    const float* __restrict__ tae,               // (B,N,T,D)
    const int*   __restrict__ tm,                // (B,N,T) bool->int32
    const float* __restrict__ etae,              // (B,1,T,D)
    const int*   __restrict__ etm,               // (B,1,T) bool->int32
    float* __restrict__ out)
{
    int i4 = blockIdx.x * blockDim.x + threadIdx.x;
    if (i4 >= TOTAL4) return;
    int i = i4 * 4;

    float4 v;
    if (i < R1) {
        // mq: (b,q,n,d) -> reset ? motion_query[b,n,d] : motion_queue[b,q,n,d]
        int idx = i;
        int d = idx % Dv; idx /= Dv;
        int n = idx % Nv; idx /= Nv;
        int b = idx / QMv;
        bool reset = (mask[b] == 0);
        const float* src = reset ? &motion_query[(b * Nv + n) * Dv + d]
                                 : &motion_queue[i];
        v = *reinterpret_cast<const float4*>(src);
    } else if (i < R2) {
        // pq
        int idx = i - R1;
        int d = idx % Dv; int r = idx / Dv;
        int np = r % NPv; r /= NPv;
        int b = r / QPv;
        bool reset = (mask[b] == 0);
        const float* src = reset ? &plan_query[(b * NPv + np) * Dv + d]
                                 : &plan_queue[idx];
        v = *reinterpret_cast<const float4*>(src);
    } else if (i < R3) {
        // eq
        int idx = i - R2;
        int d = idx % Dv; int r = idx / Dv;
        int b = r / QPv;
        bool reset = (mask[b] == 0);
        const float* src = reset ? &ego_status[b * Dv + d]
                                 : &ego_status_queue[idx];
        v = *reinterpret_cast<const float4*>(src);
    } else if (i < R4) {
        // per: int -> float; QM=4 so 4 consecutive elems share b
        int idx = i - R3;
        int b = idx / QMv;
        bool reset = (mask[b] == 0);
        v.x = reset ? 0.0f : (float)period[idx + 0];
        v.y = reset ? 0.0f : (float)period[idx + 1];
        v.z = reset ? 0.0f : (float)period[idx + 2];
        v.w = reset ? 0.0f : (float)period[idx + 3];
    } else if (i < R5) {
        // mm: out[b][t][n] = tm[b][n][t]; N=900 div by 4, 4 consecutive n
        int idx = i - R4;
        int n = idx % Nv; int r = idx / Nv;
        int t = r % TM1v; int b = r / TM1v;
        int base = (b * Nv + n) * Tv + t;
        v.x = tm[base + 0 * Tv] ? 1.0f : 0.0f;
        v.y = tm[base + 1 * Tv] ? 1.0f : 0.0f;
        v.z = tm[base + 2 * Tv] ? 1.0f : 0.0f;
        v.w = tm[base + 3 * Tv] ? 1.0f : 0.0f;
    } else if (i < R6) {
        // me: out[b][t][n][d] = tae[b][n][t][d]
        int idx = i - R5;
        int d = idx % Dv; int r = idx / Dv;
        int n = r % Nv; r /= Nv;
        int t = r % TM1v; int b = r / TM1v;
        v = *reinterpret_cast<const float4*>(
            &tae[((b * Nv + n) * Tv + t) * Dv + d]);
    } else if (i < R7) {
        // pm: out[b][t] = etm[b][t]; 4 consecutive (b,t) pairs
        int idx = i - R6;
        float vv[4];
        #pragma unroll
        for (int k = 0; k < 4; k++) {
            int e = idx + k;
            int t = e % TM1v; int b = e / TM1v;
            vv[k] = etm[b * Tv + t] ? 1.0f : 0.0f;
        }
        v.x = vv[0]; v.y = vv[1]; v.z = vv[2]; v.w = vv[3];
    } else {
        // pe: out[b][t][0][d] with any/all/argmin overwrite
        int idx = i - R7;
        int d = idx % Dv; int r = idx / Dv;
        int t = r % TM1v; int b = r / TM1v;

        bool anyf = false;
        #pragma unroll
        for (int bb = 0; bb < Bv; bb++) {
            #pragma unroll
            for (int tt = 0; tt < TM1v; tt++)
                anyf = anyf || (etm[bb * Tv + tt] != 0);
        }
        bool m0 = etm[b * Tv + 0] != 0;
        bool m1 = etm[b * Tv + 1] != 0;
        bool m2 = etm[b * Tv + 2] != 0;
        bool all_true = m0 && m1 && m2;
        int ff = (!m0) ? 0 : ((!m1) ? 1 : ((!m2) ? 2 : 0));

        bool overwrite = all_true || (t < ff);
        int src_t = (anyf && overwrite) ? (all_true ? (Tv - 1) : ff) : t;
        v = *reinterpret_cast<const float4*>(&etae[(b * Tv + src_t) * Dv + d]);
    }
    reinterpret_cast<float4*>(out)[i4] = v;
}

extern "C" void kernel_launch(void* const* d_in, const int* in_sizes, int n_in,
                              void* d_out, int out_size) {
    const float* motion_query     = (const float*)d_in[0];
    const float* plan_query       = (const float*)d_in[1];
    const float* ego_status       = (const float*)d_in[2];
    const float* motion_queue     = (const float*)d_in[3];
    const float* plan_queue       = (const float*)d_in[4];
    const float* ego_status_queue = (const float*)d_in[5];
    const int*   period           = (const int*)d_in[6];
    const int*   mask             = (const int*)d_in[7];
    const float* tae              = (const float*)d_in[8];
    const int*   tm               = (const int*)d_in[9];
    const float* etae             = (const float*)d_in[10];
    const int*   etm              = (const int*)d_in[11];
    float* out = (float*)d_out;

    const int threads = 256;
    const int blocks = (TOTAL4 + threads - 1) / threads;
    state_queue_kernel<<<blocks, threads>>>(
        motion_query, plan_query, ego_status, motion_queue, plan_queue,
        ego_status_queue, period, mask, tae, tm, etae, etm, out);
}

// round 3
// speedup vs baseline: 1.0416x; 1.0416x over previous
#include <cuda_runtime.h>

// StateQueue: pure data movement. Shapes fixed.
#define Bv   16
#define Nv   900
#define Dv   256
#define QMv  4
#define QPv  4
#define NPv  6
#define Tv   4
#define TM1v 3

// Region sizes (float elements)
#define S_MQ  (Bv*QMv*Nv*Dv)   /* 3,686,400 */
#define S_PQ  (Bv*QPv*NPv*Dv)  /*    98,304 */
#define S_EQ  (Bv*QPv*Dv)      /*    16,384 */
#define S_PER (Bv*QMv)         /*        64 */
#define S_MM  (Bv*TM1v*Nv)     /*    43,200 */
#define S_ME  (Bv*TM1v*Nv*Dv)  /* 11,059,200 */
#define S_PM  (Bv*TM1v)        /*        48 */
#define S_PE  (Bv*TM1v*Dv)     /*    12,288 */

// Output offsets
#define O_MQ  0
#define O_PQ  (O_MQ + S_MQ)
#define O_EQ  (O_PQ + S_PQ)
#define O_PER (O_EQ + S_EQ)
#define O_MM  (O_PER + S_PER)
#define O_ME  (O_MM + S_MM)
#define O_PM  (O_ME + S_ME)
#define O_PE  (O_PM + S_PM)

// Per-block chunk: 256 threads x 4 float4 = 4096 floats (16 KB)
#define CHUNK 4096

// Block counts per region (ceil(S/CHUNK))
#define B_MQ  (S_MQ / CHUNK)              /* 900 exact  */
#define B_PQ  (S_PQ / CHUNK)              /* 24 exact   */
#define B_EQ  (S_EQ / CHUNK)              /* 4 exact    */
#define B_PER 1                           /* tail       */
#define B_MM  ((S_MM + CHUNK - 1)/CHUNK)  /* 11, tail   */
#define B_ME  (S_ME / CHUNK)              /* 2700 exact */
#define B_PM  1                           /* tail       */
#define B_PE  (S_PE / CHUNK)              /* 3 exact    */

#define E_MQ  (B_MQ)
#define E_PQ  (E_MQ + B_PQ)
#define E_EQ  (E_PQ + B_EQ)
#define E_PER (E_EQ + B_PER)
#define E_MM  (E_PER + B_MM)
#define E_ME  (E_MM + B_ME)
#define E_PM  (E_ME + B_PM)
#define E_PE  (E_PM + B_PE)
#define NBLOCKS E_PE

__global__ __launch_bounds__(256) void state_queue_kernel(
    const float* __restrict__ motion_query,      // (B,N,D)
    const float* __restrict__ plan_query,        // (B,NP,D)
    const float* __restrict__ ego_status,        // (B,D)
    const float* __restrict__ motion_queue,      // (B,QM,N,D)
    const float* __restrict__ plan_queue,        // (B,QP,NP,D)
    const float* __restrict__ ego_status_queue,  // (B,QP,D)
    const int*   __restrict__ period,            // (B,QM)
    const int*   __restrict__ mask,              // (B,) bool->int32
    const float* __restrict__ tae,               // (B,N,T,D)
    const int*   __restrict__ tm,                // (B,N,T) bool->int32
    const float* __restrict__ etae,              // (B,1,T,D)
    const int*   __restrict__ etm,               // (B,1,T) bool->int32
    float* __restrict__ out)
{
    const int blk = blockIdx.x;
    const int tid = threadIdx.x;

    if (blk < E_MQ) {
        // ---- mq: (b,q,n,d) = keep ? motion_queue : motion_query[b,n,d]
        const int base = blk * CHUNK;
        float4 v[4];
        #pragma unroll
        for (int k = 0; k < 4; k++) {
            int e = base + (k * 256 + tid) * 4;
            int d = e & (Dv - 1);
            int r = e >> 8;
            int n = r % Nv;
            int b = r / (Nv * QMv);
            const float* src = (mask[b] != 0)
                ? &motion_queue[e]
                : &motion_query[(b * Nv + n) * Dv + d];
            v[k] = *reinterpret_cast<const float4*>(src);
        }
        #pragma unroll
        for (int k = 0; k < 4; k++) {
            int e = base + (k * 256 + tid) * 4;
            *reinterpret_cast<float4*>(&out[O_MQ + e]) = v[k];
        }
    } else if (blk < E_PQ) {
        // ---- pq
        const int base = (blk - E_MQ) * CHUNK;
        float4 v[4];
        #pragma unroll
        for (int k = 0; k < 4; k++) {
            int e = base + (k * 256 + tid) * 4;
            int d = e & (Dv - 1);
            int r = e >> 8;
            int np = r % NPv;
            int b = r / (NPv * QPv);
            const float* src = (mask[b] != 0)
                ? &plan_queue[e]
                : &plan_query[(b * NPv + np) * Dv + d];
            v[k] = *reinterpret_cast<const float4*>(src);
        }
        #pragma unroll
        for (int k = 0; k < 4; k++) {
            int e = base + (k * 256 + tid) * 4;
            *reinterpret_cast<float4*>(&out[O_PQ + e]) = v[k];
        }
    } else if (blk < E_EQ) {
        // ---- eq
        const int base = (blk - E_PQ) * CHUNK;
        float4 v[4];
        #pragma unroll
        for (int k = 0; k < 4; k++) {
            int e = base + (k * 256 + tid) * 4;
            int d = e & (Dv - 1);
            int b = (e >> 8) / QPv;
            const float* src = (mask[b] != 0)
                ? &ego_status_queue[e]
                : &ego_status[b * Dv + d];
            v[k] = *reinterpret_cast<const float4*>(src);
        }
        #pragma unroll
        for (int k = 0; k < 4; k++) {
            int e = base + (k * 256 + tid) * 4;
            *reinterpret_cast<float4*>(&out[O_EQ + e]) = v[k];
        }
    } else if (blk < E_PER) {
        // ---- per: 64 elems, QM=4 per b
        int e = tid * 4;
        if (e < S_PER) {
            int b = e >> 2;  // QM = 4
            bool keep = (mask[b] != 0);
            float4 v;
            v.x = keep ? (float)period[e + 0] : 0.0f;
            v.y = keep ? (float)period[e + 1] : 0.0f;
            v.z = keep ? (float)period[e + 2] : 0.0f;
            v.w = keep ? (float)period[e + 3] : 0.0f;
            *reinterpret_cast<float4*>(&out[O_PER + e]) = v;
        }
    } else if (blk < E_MM) {
        // ---- mm: out[b][t][n] = tm[b][n][t]
        const int base = (blk - E_PER) * CHUNK;
        #pragma unroll
        for (int k = 0; k < 4; k++) {
            int e = base + (k * 256 + tid) * 4;
            if (e < S_MM) {
                int n = e % Nv;             // N divisible by 4: same t,b for 4
                int r = e / Nv;
                int t = r % TM1v;
                int b = r / TM1v;
                int src = (b * Nv + n) * Tv + t;
                float4 v;
                v.x = tm[src + 0 * Tv] ? 1.0f : 0.0f;
                v.y = tm[src + 1 * Tv] ? 1.0f : 0.0f;
                v.z = tm[src + 2 * Tv] ? 1.0f : 0.0f;
                v.w = tm[src + 3 * Tv] ? 1.0f : 0.0f;
                *reinterpret_cast<float4*>(&out[O_MM + e]) = v;
            }
        }
    } else if (blk < E_ME) {
        // ---- me: out[b][t][n][d] = tae[b][n][t][d]
        const int base = (blk - E_MM) * CHUNK;
        float4 v[4];
        #pragma unroll
        for (int k = 0; k < 4; k++) {
            int e = base + (k * 256 + tid) * 4;
            int d = e & (Dv - 1);
            int r = e >> 8;
            int n = r % Nv;
            int t = (r / Nv) % TM1v;
            int b = r / (Nv * TM1v);
            v[k] = *reinterpret_cast<const float4*>(
                &tae[((b * Nv + n) * Tv + t) * Dv + d]);
        }
        #pragma unroll
        for (int k = 0; k < 4; k++) {
            int e = base + (k * 256 + tid) * 4;
            *reinterpret_cast<float4*>(&out[O_ME + e]) = v[k];
        }
    } else if (blk < E_PM) {
        // ---- pm: 48 elems, out[b][t] = etm[b][t]
        int e = tid * 4;
        if (e < S_PM) {
            float vv[4];
            #pragma unroll
            for (int j = 0; j < 4; j++) {
                int idx = e + j;
                int t = idx % TM1v;
                int b = idx / TM1v;
                vv[j] = etm[b * Tv + t] ? 1.0f : 0.0f;
            }
            float4 v = {vv[0], vv[1], vv[2], vv[3]};
            *reinterpret_cast<float4*>(&out[O_PM + e]) = v;
        }
    } else {
        // ---- pe: out[b][t][0][d] with any/all/argmin overwrite
        const int base = (blk - E_PM) * CHUNK;
        float4 v[4];
        // any over etm[:, :T-1] — uniform across block, cheap (L1)
        bool anyf = false;
        #pragma unroll
        for (int bb = 0; bb < Bv; bb++)
            #pragma unroll
            for (int tt = 0; tt < TM1v; tt++)
                anyf = anyf || (etm[bb * Tv + tt] != 0);
        #pragma unroll
        for (int k = 0; k < 4; k++) {
            int e = base + (k * 256 + tid) * 4;
            int d = e & (Dv - 1);
            int r = e >> 8;
            int t = r % TM1v;
            int b = r / TM1v;
            bool m0 = etm[b * Tv + 0] != 0;
            bool m1 = etm[b * Tv + 1] != 0;
            bool m2 = etm[b * Tv + 2] != 0;
            bool all_true = m0 && m1 && m2;
            int ff = (!m0) ? 0 : ((!m1) ? 1 : ((!m2) ? 2 : 0));
            bool overwrite = all_true || (t < ff);
            int src_t = (anyf && overwrite) ? (all_true ? (Tv - 1) : ff) : t;
            v[k] = *reinterpret_cast<const float4*>(
                &etae[(b * Tv + src_t) * Dv + d]);
        }
        #pragma unroll
        for (int k = 0; k < 4; k++) {
            int e = base + (k * 256 + tid) * 4;
            *reinterpret_cast<float4*>(&out[O_PE + e]) = v[k];
        }
    }
}

extern "C" void kernel_launch(void* const* d_in, const int* in_sizes, int n_in,
                              void* d_out, int out_size) {
    const float* motion_query     = (const float*)d_in[0];
    const float* plan_query       = (const float*)d_in[1];
    const float* ego_status       = (const float*)d_in[2];
    const float* motion_queue     = (const float*)d_in[3];
    const float* plan_queue       = (const float*)d_in[4];
    const float* ego_status_queue = (const float*)d_in[5];
    const int*   period           = (const int*)d_in[6];
    const int*   mask             = (const int*)d_in[7];
    const float* tae              = (const float*)d_in[8];
    const int*   tm               = (const int*)d_in[9];
    const float* etae             = (const float*)d_in[10];
    const int*   etm              = (const int*)d_in[11];
    float* out = (float*)d_out;

    state_queue_kernel<<<NBLOCKS, 256>>>(
        motion_query, plan_query, ego_status, motion_queue, plan_queue,
        ego_status_queue, period, mask, tae, tm, etae, etm, out);
}

// round 4
// speedup vs baseline: 1.0879x; 1.0444x over previous
#include <cuda_runtime.h>

// StateQueue: pure data movement. Shapes fixed.
#define Bv   16
#define Nv   900
#define Dv   256
#define QMv  4
#define QPv  4
#define NPv  6
#define Tv   4
#define TM1v 3

// Region sizes (float elements)
#define S_MQ  (Bv*QMv*Nv*Dv)   /* 3,686,400 */
#define S_PQ  (Bv*QPv*NPv*Dv)  /*    98,304 */
#define S_EQ  (Bv*QPv*Dv)      /*    16,384 */
#define S_PER (Bv*QMv)         /*        64 */
#define S_MM  (Bv*TM1v*Nv)     /*    43,200 */
#define S_ME  (Bv*TM1v*Nv*Dv)  /* 11,059,200 */
#define S_PM  (Bv*TM1v)        /*        48 */
#define S_PE  (Bv*TM1v*Dv)     /*    12,288 */

// Output offsets
#define O_MQ  0
#define O_PQ  (O_MQ + S_MQ)
#define O_EQ  (O_PQ + S_PQ)
#define O_PER (O_EQ + S_EQ)
#define O_MM  (O_PER + S_PER)
#define O_ME  (O_MM + S_MM)
#define O_PM  (O_ME + S_ME)
#define O_PE  (O_PM + S_PM)

// Per-block chunk: 256 threads x 8 float4 = 8192 floats (32 KB)
#define KITER 8
#define CHUNK (256 * KITER * 4)

#define B_MQ  (S_MQ / CHUNK)              /* 450 exact  */
#define B_PQ  (S_PQ / CHUNK)              /* 12 exact   */
#define B_EQ  (S_EQ / CHUNK)              /* 2 exact    */
#define B_PER 1
#define B_MM  ((S_MM + CHUNK - 1)/CHUNK)  /* 6, tail    */
#define B_ME  (S_ME / CHUNK)              /* 1350 exact */
#define B_PM  1
#define B_PE  ((S_PE + CHUNK - 1)/CHUNK)  /* 2, tail    */

#define E_MQ  (B_MQ)
#define E_PQ  (E_MQ + B_PQ)
#define E_EQ  (E_PQ + B_EQ)
#define E_PER (E_EQ + B_PER)
#define E_MM  (E_PER + B_MM)
#define E_ME  (E_MM + B_ME)
#define E_PM  (E_ME + B_PM)
#define E_PE  (E_PM + B_PE)
#define NBLOCKS E_PE

__global__ __launch_bounds__(256) void state_queue_kernel(
    const float* __restrict__ motion_query,      // (B,N,D)
    const float* __restrict__ plan_query,        // (B,NP,D)
    const float* __restrict__ ego_status,        // (B,D)
    const float* __restrict__ motion_queue,      // (B,QM,N,D)
    const float* __restrict__ plan_queue,        // (B,QP,NP,D)
    const float* __restrict__ ego_status_queue,  // (B,QP,D)
    const int*   __restrict__ period,            // (B,QM)
    const int*   __restrict__ mask,              // (B,) bool->int32
    const float* __restrict__ tae,               // (B,N,T,D)
    const int*   __restrict__ tm,                // (B,N,T) bool->int32
    const float* __restrict__ etae,              // (B,1,T,D)
    const int*   __restrict__ etm,               // (B,1,T) bool->int32
    float* __restrict__ out)
{
    const int blk = blockIdx.x;
    const int tid = threadIdx.x;

    if (blk < E_MQ) {
        // ---- mq: (b,q,n,d) = keep ? motion_queue : motion_query[b,n,d]
        const int base = blk * CHUNK;
        float4 v[KITER];
        #pragma unroll
        for (int k = 0; k < KITER; k++) {
            int e = base + (k * 256 + tid) * 4;
            int d = e & (Dv - 1);
            int r = e >> 8;
            int n = r % Nv;
            int b = r / (Nv * QMv);
            const float4* src = (mask[b] != 0)
                ? reinterpret_cast<const float4*>(&motion_queue[e])
                : reinterpret_cast<const float4*>(&motion_query[(b * Nv + n) * Dv + d]);
            v[k] = __ldcs(src);
        }
        #pragma unroll
        for (int k = 0; k < KITER; k++) {
            int e = base + (k * 256 + tid) * 4;
            __stcs(reinterpret_cast<float4*>(&out[O_MQ + e]), v[k]);
        }
    } else if (blk < E_PQ) {
        // ---- pq
        const int base = (blk - E_MQ) * CHUNK;
        float4 v[KITER];
        #pragma unroll
        for (int k = 0; k < KITER; k++) {
            int e = base + (k * 256 + tid) * 4;
            int d = e & (Dv - 1);
            int r = e >> 8;
            int np = r % NPv;
            int b = r / (NPv * QPv);
            const float4* src = (mask[b] != 0)
                ? reinterpret_cast<const float4*>(&plan_queue[e])
                : reinterpret_cast<const float4*>(&plan_query[(b * NPv + np) * Dv + d]);
            v[k] = __ldcs(src);
        }
        #pragma unroll
        for (int k = 0; k < KITER; k++) {
            int e = base + (k * 256 + tid) * 4;
            __stcs(reinterpret_cast<float4*>(&out[O_PQ + e]), v[k]);
        }
    } else if (blk < E_EQ) {
        // ---- eq
        const int base = (blk - E_PQ) * CHUNK;
        float4 v[KITER];
        #pragma unroll
        for (int k = 0; k < KITER; k++) {
            int e = base + (k * 256 + tid) * 4;
            int d = e & (Dv - 1);
            int b = (e >> 8) / QPv;
            const float4* src = (mask[b] != 0)
                ? reinterpret_cast<const float4*>(&ego_status_queue[e])
                : reinterpret_cast<const float4*>(&ego_status[b * Dv + d]);
            v[k] = __ldcs(src);
        }
        #pragma unroll
        for (int k = 0; k < KITER; k++) {
            int e = base + (k * 256 + tid) * 4;
            __stcs(reinterpret_cast<float4*>(&out[O_EQ + e]), v[k]);
        }
    } else if (blk < E_PER) {
        // ---- per: 64 elems
        int e = tid * 4;
        if (e < S_PER) {
            int b = e >> 2;  // QM = 4
            bool keep = (mask[b] != 0);
            float4 v;
            v.x = keep ? (float)period[e + 0] : 0.0f;
            v.y = keep ? (float)period[e + 1] : 0.0f;
            v.z = keep ? (float)period[e + 2] : 0.0f;
            v.w = keep ? (float)period[e + 3] : 0.0f;
            *reinterpret_cast<float4*>(&out[O_PER + e]) = v;
        }
    } else if (blk < E_MM) {
        // ---- mm: out[b][t][n] = tm[b][n][t]
        const int base = (blk - E_PER) * CHUNK;
        #pragma unroll
        for (int k = 0; k < KITER; k++) {
            int e = base + (k * 256 + tid) * 4;
            if (e < S_MM) {
                int n = e % Nv;             // N divisible by 4: same t,b for 4
                int r = e / Nv;
                int t = r % TM1v;
                int b = r / TM1v;
                int src = (b * Nv + n) * Tv + t;
                float4 v;
                v.x = tm[src + 0 * Tv] ? 1.0f : 0.0f;
                v.y = tm[src + 1 * Tv] ? 1.0f : 0.0f;
                v.z = tm[src + 2 * Tv] ? 1.0f : 0.0f;
                v.w = tm[src + 3 * Tv] ? 1.0f : 0.0f;
                __stcs(reinterpret_cast<float4*>(&out[O_MM + e]), v);
            }
        }
    } else if (blk < E_ME) {
        // ---- me: out[b][t][n][d] = tae[b][n][t][d]
        const int base = (blk - E_MM) * CHUNK;
        float4 v[KITER];
        #pragma unroll
        for (int k = 0; k < KITER; k++) {
            int e = base + (k * 256 + tid) * 4;
            int d = e & (Dv - 1);
            int r = e >> 8;
            int n = r % Nv;
            int t = (r / Nv) % TM1v;
            int b = r / (Nv * TM1v);
            v[k] = __ldcs(reinterpret_cast<const float4*>(
                &tae[((b * Nv + n) * Tv + t) * Dv + d]));
        }
        #pragma unroll
        for (int k = 0; k < KITER; k++) {
            int e = base + (k * 256 + tid) * 4;
            __stcs(reinterpret_cast<float4*>(&out[O_ME + e]), v[k]);
        }
    } else if (blk < E_PM) {
        // ---- pm: 48 elems, out[b][t] = etm[b][t]
        int e = tid * 4;
        if (e < S_PM) {
            float vv[4];
            #pragma unroll
            for (int j = 0; j < 4; j++) {
                int idx = e + j;
                int t = idx % TM1v;
                int b = idx / TM1v;
                vv[j] = etm[b * Tv + t] ? 1.0f : 0.0f;
            }
            float4 v = {vv[0], vv[1], vv[2], vv[3]};
            *reinterpret_cast<float4*>(&out[O_PM + e]) = v;
        }
    } else {
        // ---- pe: out[b][t][0][d] with any/all/argmin overwrite
        const int base = (blk - E_PM) * CHUNK;
        bool anyf = false;
        #pragma unroll
        for (int bb = 0; bb < Bv; bb++)
            #pragma unroll
            for (int tt = 0; tt < TM1v; tt++)
                anyf = anyf || (etm[bb * Tv + tt] != 0);
        #pragma unroll
        for (int k = 0; k < KITER; k++) {
            int e = base + (k * 256 + tid) * 4;
            if (e < S_PE) {
                int d = e & (Dv - 1);
                int r = e >> 8;
                int t = r % TM1v;
                int b = r / TM1v;
                bool m0 = etm[b * Tv + 0] != 0;
                bool m1 = etm[b * Tv + 1] != 0;
                bool m2 = etm[b * Tv + 2] != 0;
                bool all_true = m0 && m1 && m2;
                int ff = (!m0) ? 0 : ((!m1) ? 1 : ((!m2) ? 2 : 0));
                bool overwrite = all_true || (t < ff);
                int src_t = (anyf && overwrite) ? (all_true ? (Tv - 1) : ff) : t;
                float4 v = *reinterpret_cast<const float4*>(
                    &etae[(b * Tv + src_t) * Dv + d]);
                __stcs(reinterpret_cast<float4*>(&out[O_PE + e]), v);
            }
        }
    }
}

extern "C" void kernel_launch(void* const* d_in, const int* in_sizes, int n_in,
                              void* d_out, int out_size) {
    const float* motion_query     = (const float*)d_in[0];
    const float* plan_query       = (const float*)d_in[1];
    const float* ego_status       = (const float*)d_in[2];
    const float* motion_queue     = (const float*)d_in[3];
    const float* plan_queue       = (const float*)d_in[4];
    const float* ego_status_queue = (const float*)d_in[5];
    const int*   period           = (const int*)d_in[6];
    const int*   mask             = (const int*)d_in[7];
    const float* tae              = (const float*)d_in[8];
    const int*   tm               = (const int*)d_in[9];
    const float* etae             = (const float*)d_in[10];
    const int*   etm              = (const int*)d_in[11];
    float* out = (float*)d_out;

    state_queue_kernel<<<NBLOCKS, 256>>>(
        motion_query, plan_query, ego_status, motion_queue, plan_queue,
        ego_status_queue, period, mask, tae, tm, etae, etm, out);
}